// round 13
// baseline (speedup 1.0000x reference)
#include <cuda_runtime.h>
#include <cuda_fp16.h>
#include <math.h>
#include <stdint.h>

// ---------------------------------------------------------------------------
// Problem constants
// ---------------------------------------------------------------------------
#define NB     4
#define LSEQ   8192
#define CD     256
#define NH     8
#define HD     32
#define MTOT   (NB * LSEQ)          // 32768
#define MC     ((size_t)MTOT * CD)  // 8388608
#define MC2    ((size_t)MTOT * 2 * CD)

// ---------------------------------------------------------------------------
// Scratch (device globals) — all-fp16 activation chain
// ---------------------------------------------------------------------------
__device__ float g_KV[NB * NH * HD * HD];
__device__ float g_Ksum[NB * NH * HD];

__device__ __half g_x16[MC];              // x
__device__ __half g_s16[MC];              // source
__device__ __half g_q16[MC];              // Q (elu+1)
__device__ __half g_k16[MC];              // K (elu+1)
__device__ __half g_v16[MC];              // V
__device__ __half g_a16[MC];              // attn out
__device__ __half g_mg16[MC];             // merge out (pre-LN1)
__device__ __half g_m16[MC];              // msg after LN1
__device__ __half g_h16[MC2];             // MLP hidden
__device__ __half g_m2_16[MC];            // mlp2 out (pre-LN2)

__device__ __half g_Wq16[CD * CD];
__device__ __half g_Wk16[CD * CD];
__device__ __half g_Wv16[CD * CD];
__device__ __half g_Wm16[CD * CD];
__device__ __half g_W116[2 * CD * 2 * CD];
__device__ __half g_W216[CD * 2 * CD];

// ---------------------------------------------------------------------------
// Helpers
// ---------------------------------------------------------------------------
__device__ __forceinline__ uint32_t smem_u32(const void* p) {
    return (uint32_t)__cvta_generic_to_shared(p);
}
__device__ __forceinline__ void cp16(uint32_t dst, const void* src) {
    asm volatile("cp.async.ca.shared.global [%0], [%1], 16;" :: "r"(dst), "l"(src));
}
__device__ __forceinline__ void cp_commit() {
    asm volatile("cp.async.commit_group;");
}
template <int N>
__device__ __forceinline__ void cp_wait() {
    asm volatile("cp.async.wait_group %0;" :: "n"(N));
}
__device__ __forceinline__ void ldmx4(uint32_t* r, uint32_t addr) {
    asm volatile("ldmatrix.sync.aligned.m8n8.x4.shared.b16 {%0,%1,%2,%3}, [%4];"
                 : "=r"(r[0]), "=r"(r[1]), "=r"(r[2]), "=r"(r[3]) : "r"(addr));
}
__device__ __forceinline__ void ldmx4t(uint32_t* r, uint32_t addr) {
    asm volatile("ldmatrix.sync.aligned.m8n8.x4.trans.shared.b16 {%0,%1,%2,%3}, [%4];"
                 : "=r"(r[0]), "=r"(r[1]), "=r"(r[2]), "=r"(r[3]) : "r"(addr));
}
__device__ __forceinline__ void mma16816(float* c, const uint32_t* a,
                                         uint32_t b0, uint32_t b1) {
    asm volatile(
        "mma.sync.aligned.m16n8k16.row.col.f32.f16.f16.f32 "
        "{%0,%1,%2,%3}, {%4,%5,%6,%7}, {%8,%9}, {%0,%1,%2,%3};"
        : "+f"(c[0]), "+f"(c[1]), "+f"(c[2]), "+f"(c[3])
        : "r"(a[0]), "r"(a[1]), "r"(a[2]), "r"(a[3]), "r"(b0), "r"(b1));
}
__device__ __forceinline__ uint32_t pack2h(float a, float b) {
    __half2 h = __floats2half2_rn(a, b);
    return *(uint32_t*)&h;
}

// ---------------------------------------------------------------------------
// Activation conversion: fp32 -> fp16.  blockIdx.y: 0 = x, 1 = source.
// ---------------------------------------------------------------------------
__global__ void __launch_bounds__(256)
cvt_act_kernel(const float* __restrict__ x, const float* __restrict__ src)
{
    const size_t i = (size_t)blockIdx.x * blockDim.x + threadIdx.x;
    const float* s = blockIdx.y ? src : x;
    __half* o = blockIdx.y ? g_s16 : g_x16;
    float4 v = ((const float4*)s)[i];
    uint2 H;
    H.x = pack2h(v.x, v.y);
    H.y = pack2h(v.z, v.w);
    ((uint2*)o)[i] = H;
}

// ---------------------------------------------------------------------------
// Weight conversion fp32 -> fp16 (163840 float4) + zero KV accumulators.
// ---------------------------------------------------------------------------
__global__ void __launch_bounds__(256)
cvt_w_kernel(const float* __restrict__ Wq, const float* __restrict__ Wk,
             const float* __restrict__ Wv, const float* __restrict__ Wm,
             const float* __restrict__ W1, const float* __restrict__ W2)
{
    const int i = blockIdx.x * blockDim.x + threadIdx.x;
    if (i < NB * NH * HD * HD) g_KV[i] = 0.0f;
    if (i < NB * NH * HD)      g_Ksum[i] = 0.0f;
    const float* s; __half* d; int j;
    if      (i <  16384) { s = Wq; d = g_Wq16; j = i; }
    else if (i <  32768) { s = Wk; d = g_Wk16; j = i - 16384; }
    else if (i <  49152) { s = Wv; d = g_Wv16; j = i - 32768; }
    else if (i <  65536) { s = Wm; d = g_Wm16; j = i - 49152; }
    else if (i < 131072) { s = W1; d = g_W116; j = i - 65536; }
    else                 { s = W2; d = g_W216; j = i - 131072; }
    float4 v = ((const float4*)s)[j];
    uint2 o;
    o.x = pack2h(v.x, v.y);
    o.y = pack2h(v.z, v.w);
    ((uint2*)d)[j] = o;
}

// ---------------------------------------------------------------------------
// fp16 GEMM core, BK=64:
//   BM=128, BN=128, BK=64; 8 warps (2x4), warp tile 64x32; 256 threads;
//   cp.async 3-stage ring, single __syncthreads per k-tile; fp16 output.
// ---------------------------------------------------------------------------
enum { ACT_NONE = 0, ACT_ELU1 = 1, ACT_RELU = 2 };

#define BK       64
#define ROWB     144           // 128B data + 16B pad (bank stride 4 — conflict-free)
#define TILE_B   (128 * ROWB)  // 18432
#define STAGE_B  (2 * TILE_B)  // 36864
#define A_OFF    0
#define B_OFF    TILE_B
#define NSTAGE   3
#define SMEM_SZ  (NSTAGE * STAGE_B) // 110592

__device__ __forceinline__ void
gemm_core(const __half* __restrict__ A1, const __half* __restrict__ A2,
          int K1, int K, const __half* __restrict__ Wh,
          __half* __restrict__ Ch, int NT, int act, char* smem, int m0, int n0)
{
    const uint32_t sbase = smem_u32(smem);

    const int tid  = threadIdx.x;
    const int wid  = tid >> 5;
    const int lane = tid & 31;

    const int wm = (wid >> 2) * 64;   // warp m offset (0/64)
    const int wn = (wid & 3) * 32;    // warp n offset (0..96)

    const int aRow  = wm + (lane & 15);
    const int aHalf = ((lane >> 4) & 1) * 8;
    const int bRow  = wn + (lane & 7) + ((lane >> 4) & 1) * 8;
    const int bHalf = ((lane >> 3) & 1) * 8;

    // gmem->smem: threads 0-127 load A rows, 128-255 load B rows (128B each)
    const int lr  = tid & 127;
    const bool isB = tid >= 128;

    float acc[4][4][4];
#pragma unroll
    for (int i = 0; i < 4; ++i)
#pragma unroll
        for (int j = 0; j < 4; ++j)
#pragma unroll
            for (int r = 0; r < 4; ++r) acc[i][j][r] = 0.0f;

    const int KT = K / BK;

    auto prefetch = [&](int kt, int st) {
        const int kg0 = kt * BK;
        const char* gsrc;
        if (isB) {
            gsrc = (const char*)(Wh + (size_t)(n0 + lr) * K + kg0);
        } else {
            const __half* pA; int lda, kb;
            if (A2 != nullptr && kg0 >= K1) { pA = A2; lda = K - K1; kb = kg0 - K1; }
            else                            { pA = A1; lda = K1;     kb = kg0; }
            gsrc = (const char*)(pA + (size_t)(m0 + lr) * lda + kb);
        }
        const uint32_t sd = sbase + st * STAGE_B + (isB ? B_OFF : A_OFF) + lr * ROWB;
#pragma unroll
        for (int c = 0; c < 128; c += 16)
            cp16(sd + c, gsrc + c);
        cp_commit();
    };

    prefetch(0, 0);
    prefetch(1, 1);

    int st = 0;
    for (int kt = 0; kt < KT; ++kt) {
        cp_wait<1>();
        __syncthreads();

        const uint32_t base = sbase + st * STAGE_B;
#pragma unroll
        for (int ks = 0; ks < 4; ++ks) {
            uint32_t bf[2][4];
#pragma unroll
            for (int nf = 0; nf < 2; ++nf)
                ldmx4(bf[nf], base + B_OFF + (uint32_t)((bRow + nf * 16) * ROWB) +
                              (uint32_t)(ks * 16 + bHalf) * 2);
            uint32_t af[4][4];
#pragma unroll
            for (int mf = 0; mf < 4; ++mf)
                ldmx4(af[mf], base + A_OFF + (uint32_t)((aRow + mf * 16) * ROWB) +
                              (uint32_t)(ks * 16 + aHalf) * 2);
#pragma unroll
            for (int mf = 0; mf < 4; ++mf)
#pragma unroll
                for (int nr = 0; nr < 4; ++nr)
                    mma16816(acc[mf][nr], af[mf], bf[nr >> 1][(nr & 1) * 2],
                             bf[nr >> 1][(nr & 1) * 2 + 1]);
        }

        // prefetch into slot (kt+2)%3 == (kt-1)%3 — safe: sync at top of this
        // iteration guarantees all threads finished compute of kt-1.
        if (kt + 2 < KT) prefetch(kt + 2, (kt + 2) % NSTAGE);
        else             cp_commit();   // keep group accounting aligned

        st = (st + 1) % NSTAGE;
    }

    // ---- epilogue (fp16 stores) ----
    const int g  = lane >> 2;
    const int qd = lane & 3;
#pragma unroll
    for (int mf = 0; mf < 4; ++mf) {
#pragma unroll
        for (int nr = 0; nr < 4; ++nr) {
#pragma unroll
            for (int half = 0; half < 2; ++half) {
                const int row = m0 + wm + mf * 16 + g + half * 8;
                const int col = n0 + wn + nr * 8 + qd * 2;
                float v0 = acc[mf][nr][half * 2 + 0];
                float v1 = acc[mf][nr][half * 2 + 1];
                if (act == ACT_ELU1) {
                    v0 = (v0 > 0.f) ? v0 + 1.f : expf(v0);
                    v1 = (v1 > 0.f) ? v1 + 1.f : expf(v1);
                } else if (act == ACT_RELU) {
                    v0 = fmaxf(v0, 0.f); v1 = fmaxf(v1, 0.f);
                }
                *(uint32_t*)&Ch[(size_t)row * NT + col] = pack2h(v0, v1);
            }
        }
    }
}

// Merged Q/K/V launch: blockIdx.z selects {Q, K, V}; all outputs fp16.
__global__ void __launch_bounds__(256)
gemm_qkv_kernel()
{
    extern __shared__ char smem[];
    const int z  = blockIdx.z;
    const int m0 = blockIdx.y * 128;
    const int n0 = blockIdx.x * 128;
    const __half* A = (z == 0) ? g_x16 : g_s16;
    const __half* W = (z == 0) ? g_Wq16 : (z == 1) ? g_Wk16 : g_Wv16;
    __half* C       = (z == 0) ? g_q16  : (z == 1) ? g_k16  : g_v16;
    const int act   = (z == 2) ? ACT_NONE : ACT_ELU1;
    gemm_core(A, nullptr, CD, CD, W, C, CD, act, smem, m0, n0);
}

// Generic single-GEMM launch.
__global__ void __launch_bounds__(256)
gemm_one_kernel(const __half* __restrict__ A1, const __half* __restrict__ A2,
                int K1, int K, const __half* __restrict__ Wh,
                __half* __restrict__ Ch, int NT, int act)
{
    extern __shared__ char smem[];
    gemm_core(A1, A2, K1, K, Wh, Ch, NT, act,
              smem, blockIdx.y * 128, blockIdx.x * 128);
}

// ---------------------------------------------------------------------------
// KV reduce — tensor-core K^T·V (proven R11 version).
// ---------------------------------------------------------------------------
#define KVROW 40

__global__ void __launch_bounds__(128)
kv_reduce_kernel()
{
    __shared__ __half KVsm[2][256][KVROW];

    const int nh = blockIdx.x;
    const int n  = nh / NH;
    const int h  = nh % NH;
    const int s0 = blockIdx.y * 256;
    const int tid  = threadIdx.x;
    const int wid  = tid >> 5;
    const int lane = tid & 31;

    const __half* Kb = g_k16 + (size_t)n * LSEQ * CD + (size_t)h * HD;
    const __half* Vb = g_v16 + (size_t)n * LSEQ * CD + (size_t)h * HD;

    for (int i = tid; i < 256 * 4; i += 128) {
        const int r = i >> 2;
        const int c = (i & 3) * 8;
        const size_t off = (size_t)(s0 + r) * CD + c;
        *(uint4*)&KVsm[0][r][c] = *(const uint4*)&Kb[off];
        *(uint4*)&KVsm[1][r][c] = *(const uint4*)&Vb[off];
    }
    __syncthreads();

    {
        float ksum = 0.0f;
        const int sb = wid * 64;
#pragma unroll 8
        for (int s = sb; s < sb + 64; ++s)
            ksum += __half2float(KVsm[0][s][lane]);
        atomicAdd(&g_Ksum[nh * HD + lane], ksum);
    }

    float acc[2][4][4];
#pragma unroll
    for (int i = 0; i < 2; ++i)
#pragma unroll
        for (int j = 0; j < 4; ++j)
#pragma unroll
            for (int r = 0; r < 4; ++r) acc[i][j][r] = 0.0f;

    const uint32_t kbase = smem_u32(&KVsm[0][0][0]);
    const uint32_t vbase = smem_u32(&KVsm[1][0][0]);
    const int q  = lane >> 3;
    const int i8 = lane & 7;

#pragma unroll
    for (int chunk = 0; chunk < 4; ++chunk) {
        const int sb = wid * 64 + chunk * 16;
        const int sA = sb + ((q >> 1) ? 8 : 0) + i8;
        uint32_t af[2][4];
#pragma unroll
        for (int mt = 0; mt < 2; ++mt) {
            const int col = mt * 16 + ((q & 1) ? 8 : 0);
            ldmx4t(af[mt], kbase + (uint32_t)(sA * KVROW + col) * 2);
        }
        const int sB = sb + ((q & 1) ? 8 : 0) + i8;
        uint32_t bf[2][4];
#pragma unroll
        for (int nf = 0; nf < 2; ++nf) {
            const int col = nf * 16 + ((q >> 1) ? 8 : 0);
            ldmx4t(bf[nf], vbase + (uint32_t)(sB * KVROW + col) * 2);
        }
#pragma unroll
        for (int mt = 0; mt < 2; ++mt)
#pragma unroll
            for (int nt = 0; nt < 4; ++nt)
                mma16816(acc[mt][nt], af[mt], bf[nt >> 1][(nt & 1) * 2],
                         bf[nt >> 1][(nt & 1) * 2 + 1]);
    }
    __syncthreads();

    float* Cred = (float*)&KVsm[0][0][0];
    const int g  = lane >> 2;
    const int qd = lane & 3;
#pragma unroll
    for (int mt = 0; mt < 2; ++mt)
#pragma unroll
        for (int nt = 0; nt < 4; ++nt)
#pragma unroll
            for (int c = 0; c < 4; ++c) {
                const int d = mt * 16 + g + ((c >> 1) ? 8 : 0);
                const int e = nt * 8 + qd * 2 + (c & 1);
                Cred[(wid * 32 + d) * 33 + e] = acc[mt][nt][c];
            }
    __syncthreads();

    for (int cell = tid; cell < 1024; cell += 128) {
        const int d = cell >> 5;
        const int e = cell & 31;
        const float ssum = Cred[(0 * 32 + d) * 33 + e] + Cred[(1 * 32 + d) * 33 + e]
                         + Cred[(2 * 32 + d) * 33 + e] + Cred[(3 * 32 + d) * 33 + e];
        atomicAdd(&g_KV[(size_t)nh * HD * HD + cell], ssum);
    }
}

// ---------------------------------------------------------------------------
// Attention apply: reads Q fp16; 4-row batching; warp == head.
// ---------------------------------------------------------------------------
__global__ void __launch_bounds__(256)
attn_apply_kernel()
{
    __shared__ float KVs[NH * HD * HD];
    __shared__ float KsumS[NH * HD];

    const int row0 = blockIdx.x * 64;
    const int n    = row0 / LSEQ;
    const int tid  = threadIdx.x;
    const int h    = tid >> 5;
    const int e    = tid & 31;

    const float* KVg = g_KV + (size_t)n * NH * HD * HD;
    for (int i = tid; i < NH * HD * HD / 4; i += 256)
        ((float4*)KVs)[i] = ((const float4*)KVg)[i];
    KsumS[tid] = g_Ksum[n * NH * HD + tid];
    __syncthreads();

    const float ks = KsumS[tid];
    const float* kvh = &KVs[h * HD * HD];

    for (int r = 0; r < 64; r += 4) {
        const size_t b0 = (size_t)(row0 + r) * CD;
        const float q0 = __half2float(g_q16[b0 + tid]);
        const float q1 = __half2float(g_q16[b0 + CD + tid]);
        const float q2 = __half2float(g_q16[b0 + 2 * CD + tid]);
        const float q3 = __half2float(g_q16[b0 + 3 * CD + tid]);

        float z0 = q0 * ks, z1 = q1 * ks, z2 = q2 * ks, z3 = q3 * ks;
#pragma unroll
        for (int o = 16; o > 0; o >>= 1) {
            z0 += __shfl_xor_sync(0xffffffff, z0, o);
            z1 += __shfl_xor_sync(0xffffffff, z1, o);
            z2 += __shfl_xor_sync(0xffffffff, z2, o);
            z3 += __shfl_xor_sync(0xffffffff, z3, o);
        }
        z0 = 1.0f / (z0 + 1e-6f);
        z1 = 1.0f / (z1 + 1e-6f);
        z2 = 1.0f / (z2 + 1e-6f);
        z3 = 1.0f / (z3 + 1e-6f);

        float a0 = 0.f, a1 = 0.f, a2 = 0.f, a3 = 0.f;
#pragma unroll
        for (int d = 0; d < HD; ++d) {
            const float kvv = kvh[d * HD + e];
            a0 = fmaf(__shfl_sync(0xffffffff, q0, d), kvv, a0);
            a1 = fmaf(__shfl_sync(0xffffffff, q1, d), kvv, a1);
            a2 = fmaf(__shfl_sync(0xffffffff, q2, d), kvv, a2);
            a3 = fmaf(__shfl_sync(0xffffffff, q3, d), kvv, a3);
        }
        g_a16[b0 + tid]          = __float2half_rn(a0 * z0);
        g_a16[b0 + CD + tid]     = __float2half_rn(a1 * z1);
        g_a16[b0 + 2 * CD + tid] = __float2half_rn(a2 * z2);
        g_a16[b0 + 3 * CD + tid] = __float2half_rn(a3 * z3);
    }
}

// ---------------------------------------------------------------------------
// LayerNorm variants (fp16 inputs)
// ---------------------------------------------------------------------------
__global__ void __launch_bounds__(256)
ln_f16_kernel(const __half* __restrict__ src, __half* __restrict__ o,
              const float* __restrict__ g, const float* __restrict__ b)
{
    const int row  = blockIdx.x * 8 + threadIdx.y;
    const int lane = threadIdx.x;
    const __half* p = src + (size_t)row * CD;

    float v[8];
    float s = 0.0f;
#pragma unroll
    for (int i = 0; i < 8; ++i) { v[i] = __half2float(p[i * 32 + lane]); s += v[i]; }
#pragma unroll
    for (int of = 16; of > 0; of >>= 1) s += __shfl_xor_sync(0xffffffff, s, of);
    const float mu = s * (1.0f / CD);

    float vs = 0.0f;
#pragma unroll
    for (int i = 0; i < 8; ++i) { const float d = v[i] - mu; vs = fmaf(d, d, vs); }
#pragma unroll
    for (int of = 16; of > 0; of >>= 1) vs += __shfl_xor_sync(0xffffffff, vs, of);
    const float rstd = rsqrtf(vs * (1.0f / CD) + 1e-7f);

#pragma unroll
    for (int i = 0; i < 8; ++i) {
        const int c = i * 32 + lane;
        o[(size_t)row * CD + c] =
            __float2half_rn((v[i] - mu) * rstd * g[c] + b[c]);
    }
}

__global__ void __launch_bounds__(256)
ln_res_kernel(const __half* __restrict__ src, const float* __restrict__ x,
              float* __restrict__ dst,
              const float* __restrict__ g, const float* __restrict__ b)
{
    const int row  = blockIdx.x * 8 + threadIdx.y;
    const int lane = threadIdx.x;
    const __half* p = src + (size_t)row * CD;

    float v[8];
    float s = 0.0f;
#pragma unroll
    for (int i = 0; i < 8; ++i) { v[i] = __half2float(p[i * 32 + lane]); s += v[i]; }
#pragma unroll
    for (int of = 16; of > 0; of >>= 1) s += __shfl_xor_sync(0xffffffff, s, of);
    const float mu = s * (1.0f / CD);

    float vs = 0.0f;
#pragma unroll
    for (int i = 0; i < 8; ++i) { const float d = v[i] - mu; vs = fmaf(d, d, vs); }
#pragma unroll
    for (int of = 16; of > 0; of >>= 1) vs += __shfl_xor_sync(0xffffffff, vs, of);
    const float rstd = rsqrtf(vs * (1.0f / CD) + 1e-7f);

#pragma unroll
    for (int i = 0; i < 8; ++i) {
        const int c = i * 32 + lane;
        dst[(size_t)row * CD + c] =
            (v[i] - mu) * rstd * g[c] + b[c] + x[(size_t)row * CD + c];
    }
}

// ---------------------------------------------------------------------------
// Launch
// ---------------------------------------------------------------------------
extern "C" void kernel_launch(void* const* d_in, const int* in_sizes, int n_in,
                              void* d_out, int out_size)
{
    const float* x      = (const float*)d_in[0];
    const float* source = (const float*)d_in[1];
    const float* Wq     = (const float*)d_in[2];
    const float* Wk     = (const float*)d_in[3];
    const float* Wv     = (const float*)d_in[4];
    const float* Wmerge = (const float*)d_in[5];
    const float* Wmlp1  = (const float*)d_in[6];
    const float* Wmlp2  = (const float*)d_in[7];
    const float* ln1_g  = (const float*)d_in[8];
    const float* ln1_b  = (const float*)d_in[9];
    const float* ln2_g  = (const float*)d_in[10];
    const float* ln2_b  = (const float*)d_in[11];
    float* out = (float*)d_out;

    __half *x16, *a16, *mg16, *m16, *h16, *m216;
    __half *W16m, *W161, *W162;
    cudaGetSymbolAddress((void**)&x16,  g_x16);
    cudaGetSymbolAddress((void**)&a16,  g_a16);
    cudaGetSymbolAddress((void**)&mg16, g_mg16);
    cudaGetSymbolAddress((void**)&m16,  g_m16);
    cudaGetSymbolAddress((void**)&h16,  g_h16);
    cudaGetSymbolAddress((void**)&m216, g_m2_16);
    cudaGetSymbolAddress((void**)&W16m, g_Wm16);
    cudaGetSymbolAddress((void**)&W161, g_W116);
    cudaGetSymbolAddress((void**)&W162, g_W216);

    static bool smem_set = false;
    if (!smem_set) {
        cudaFuncSetAttribute((const void*)gemm_qkv_kernel,
                             cudaFuncAttributeMaxDynamicSharedMemorySize, SMEM_SZ);
        cudaFuncSetAttribute((const void*)gemm_one_kernel,
                             cudaFuncAttributeMaxDynamicSharedMemorySize, SMEM_SZ);
        smem_set = true;
    }

    const int GM = MTOT / 128;
    const dim3 gqkv(2, GM, 3);
    const dim3 g256(2, GM);
    const dim3 g512(4, GM);

    // 1: convert activations (x + source) to fp16
    cvt_act_kernel<<<dim3((unsigned)(MC / 4 / 256), 2), 256>>>(x, source);
    // 2: convert all weights to fp16 + zero KV accumulators
    cvt_w_kernel<<<640, 256>>>(Wq, Wk, Wv, Wmerge, Wmlp1, Wmlp2);

    // 3: Q/K/V GEMMs in one launch (all fp16 out)
    gemm_qkv_kernel<<<gqkv, 256, SMEM_SZ>>>();

    // 4: KV / Ksum via tensor cores
    kv_reduce_kernel<<<dim3(NB * NH, LSEQ / 256), 128>>>();
    // 5: attention apply -> fp16
    attn_apply_kernel<<<MTOT / 64, 256>>>();

    // 6: msg = attn @ Wmerge^T -> fp16
    gemm_one_kernel<<<g256, 256, SMEM_SZ>>>(
        a16, nullptr, CD, CD, W16m, mg16, CD, ACT_NONE);
    // 7: LN1 -> fp16
    ln_f16_kernel<<<MTOT / 8, dim3(32, 8)>>>(mg16, m16, ln1_g, ln1_b);

    // 8: h = relu([x | msg] @ Wmlp1^T) -> fp16
    gemm_one_kernel<<<g512, 256, SMEM_SZ>>>(
        x16, m16, CD, 2 * CD, W161, h16, 2 * CD, ACT_RELU);

    // 9: msg2 = h @ Wmlp2^T -> fp16
    gemm_one_kernel<<<g256, 256, SMEM_SZ>>>(
        h16, nullptr, 2 * CD, 2 * CD, W162, m216, CD, ACT_NONE);
    // 10: out = x + LN2(msg2)
    ln_res_kernel<<<MTOT / 8, dim3(32, 8)>>>(m216, x, out, ln2_g, ln2_b);
}

// round 14
// speedup vs baseline: 1.1879x; 1.1879x over previous
#include <cuda_runtime.h>
#include <cuda_fp16.h>
#include <math.h>
#include <stdint.h>

// ---------------------------------------------------------------------------
// Problem constants
// ---------------------------------------------------------------------------
#define NB     4
#define LSEQ   8192
#define CD     256
#define NH     8
#define HD     32
#define MTOT   (NB * LSEQ)          // 32768
#define MC     ((size_t)MTOT * CD)  // 8388608
#define MC2    ((size_t)MTOT * 2 * CD)

// ---------------------------------------------------------------------------
// Scratch (device globals) — all-fp16 activation chain
// ---------------------------------------------------------------------------
__device__ float g_KV[NB * NH * HD * HD];
__device__ float g_Ksum[NB * NH * HD];

__device__ __half g_x16[MC];              // x
__device__ __half g_s16[MC];              // source
__device__ __half g_q16[MC];              // Q (elu+1)
__device__ __half g_k16[MC];              // K (elu+1)
__device__ __half g_v16[MC];              // V
__device__ __half g_a16[MC];              // attn out
__device__ __half g_mg16[MC];             // merge out (pre-LN1)
__device__ __half g_m16[MC];              // msg after LN1
__device__ __half g_h16[MC2];             // MLP hidden
__device__ __half g_m2_16[MC];            // mlp2 out (pre-LN2)

__device__ __half g_Wq16[CD * CD];
__device__ __half g_Wk16[CD * CD];
__device__ __half g_Wv16[CD * CD];
__device__ __half g_Wm16[CD * CD];
__device__ __half g_W116[2 * CD * 2 * CD];
__device__ __half g_W216[CD * 2 * CD];

// ---------------------------------------------------------------------------
// Helpers
// ---------------------------------------------------------------------------
__device__ __forceinline__ uint32_t smem_u32(const void* p) {
    return (uint32_t)__cvta_generic_to_shared(p);
}
__device__ __forceinline__ void cp16(uint32_t dst, const void* src) {
    asm volatile("cp.async.ca.shared.global [%0], [%1], 16;" :: "r"(dst), "l"(src));
}
__device__ __forceinline__ void cp_commit() {
    asm volatile("cp.async.commit_group;");
}
template <int N>
__device__ __forceinline__ void cp_wait() {
    asm volatile("cp.async.wait_group %0;" :: "n"(N));
}
__device__ __forceinline__ void ldmx4(uint32_t* r, uint32_t addr) {
    asm volatile("ldmatrix.sync.aligned.m8n8.x4.shared.b16 {%0,%1,%2,%3}, [%4];"
                 : "=r"(r[0]), "=r"(r[1]), "=r"(r[2]), "=r"(r[3]) : "r"(addr));
}
__device__ __forceinline__ void ldmx4t(uint32_t* r, uint32_t addr) {
    asm volatile("ldmatrix.sync.aligned.m8n8.x4.trans.shared.b16 {%0,%1,%2,%3}, [%4];"
                 : "=r"(r[0]), "=r"(r[1]), "=r"(r[2]), "=r"(r[3]) : "r"(addr));
}
__device__ __forceinline__ void mma16816(float* c, const uint32_t* a,
                                         uint32_t b0, uint32_t b1) {
    asm volatile(
        "mma.sync.aligned.m16n8k16.row.col.f32.f16.f16.f32 "
        "{%0,%1,%2,%3}, {%4,%5,%6,%7}, {%8,%9}, {%0,%1,%2,%3};"
        : "+f"(c[0]), "+f"(c[1]), "+f"(c[2]), "+f"(c[3])
        : "r"(a[0]), "r"(a[1]), "r"(a[2]), "r"(a[3]), "r"(b0), "r"(b1));
}
__device__ __forceinline__ uint32_t pack2h(float a, float b) {
    __half2 h = __floats2half2_rn(a, b);
    return *(uint32_t*)&h;
}

// ---------------------------------------------------------------------------
// Activation conversion: fp32 -> fp16.  blockIdx.y: 0 = x, 1 = source.
// ---------------------------------------------------------------------------
__global__ void __launch_bounds__(256)
cvt_act_kernel(const float* __restrict__ x, const float* __restrict__ src)
{
    const size_t i = (size_t)blockIdx.x * blockDim.x + threadIdx.x;
    const float* s = blockIdx.y ? src : x;
    __half* o = blockIdx.y ? g_s16 : g_x16;
    float4 v = ((const float4*)s)[i];
    uint2 H;
    H.x = pack2h(v.x, v.y);
    H.y = pack2h(v.z, v.w);
    ((uint2*)o)[i] = H;
}

// ---------------------------------------------------------------------------
// Weight conversion fp32 -> fp16 (163840 float4) + zero KV accumulators.
// ---------------------------------------------------------------------------
__global__ void __launch_bounds__(256)
cvt_w_kernel(const float* __restrict__ Wq, const float* __restrict__ Wk,
             const float* __restrict__ Wv, const float* __restrict__ Wm,
             const float* __restrict__ W1, const float* __restrict__ W2)
{
    const int i = blockIdx.x * blockDim.x + threadIdx.x;
    if (i < NB * NH * HD * HD) g_KV[i] = 0.0f;
    if (i < NB * NH * HD)      g_Ksum[i] = 0.0f;
    const float* s; __half* d; int j;
    if      (i <  16384) { s = Wq; d = g_Wq16; j = i; }
    else if (i <  32768) { s = Wk; d = g_Wk16; j = i - 16384; }
    else if (i <  49152) { s = Wv; d = g_Wv16; j = i - 32768; }
    else if (i <  65536) { s = Wm; d = g_Wm16; j = i - 49152; }
    else if (i < 131072) { s = W1; d = g_W116; j = i - 65536; }
    else                 { s = W2; d = g_W216; j = i - 131072; }
    float4 v = ((const float4*)s)[j];
    uint2 o;
    o.x = pack2h(v.x, v.y);
    o.y = pack2h(v.z, v.w);
    ((uint2*)d)[j] = o;
}

// ---------------------------------------------------------------------------
// fp16 GEMM core (proven R11 config, fp16 output):
//   BM=128, BN=128, BK=32; 8 warps (2x4), warp tile 64x32; 256 threads;
//   cp.async 3-stage ring, single __syncthreads per k-tile.
// ---------------------------------------------------------------------------
enum { ACT_NONE = 0, ACT_ELU1 = 1, ACT_RELU = 2 };

#define BK       32
#define ROWB     80            // smem row stride bytes (64B data + 16B pad)
#define TILE_B   (128 * ROWB)  // 10240
#define STAGE_B  (2 * TILE_B)  // 20480
#define A_OFF    0
#define B_OFF    TILE_B
#define NSTAGE   3
#define SMEM_SZ  (NSTAGE * STAGE_B) // 61440

__device__ __forceinline__ void
gemm_core(const __half* __restrict__ A1, const __half* __restrict__ A2,
          int K1, int K, const __half* __restrict__ Wh,
          __half* __restrict__ Ch, int NT, int act, char* smem, int m0, int n0)
{
    const uint32_t sbase = smem_u32(smem);

    const int tid  = threadIdx.x;
    const int wid  = tid >> 5;
    const int lane = tid & 31;

    const int wm = (wid >> 2) * 64;   // warp m offset (0/64)
    const int wn = (wid & 3) * 32;    // warp n offset (0..96)

    const int aRow  = wm + (lane & 15);
    const int aHalf = ((lane >> 4) & 1) * 8;
    const int bRow  = wn + (lane & 7) + ((lane >> 4) & 1) * 8;
    const int bHalf = ((lane >> 3) & 1) * 8;

    const int lr  = tid >> 1;
    const int lqb = (tid & 1) * 32;

    float acc[4][4][4];
#pragma unroll
    for (int i = 0; i < 4; ++i)
#pragma unroll
        for (int j = 0; j < 4; ++j)
#pragma unroll
            for (int r = 0; r < 4; ++r) acc[i][j][r] = 0.0f;

    const int KT = K / BK;

    auto prefetch = [&](int kt, int st) {
        const int kg0 = kt * BK;
        const __half* pA; int lda, kb;
        if (A2 != nullptr && kg0 >= K1) { pA = A2; lda = K - K1; kb = kg0 - K1; }
        else                            { pA = A1; lda = K1;     kb = kg0; }

        const uint32_t sd = sbase + st * STAGE_B + lr * ROWB + lqb;
        const char* gA = (const char*)(pA + (size_t)(m0 + lr) * lda + kb) + lqb;
        const char* gB = (const char*)(Wh + (size_t)(n0 + lr) * K + kg0) + lqb;
        cp16(sd + A_OFF, gA);  cp16(sd + A_OFF + 16, gA + 16);
        cp16(sd + B_OFF, gB);  cp16(sd + B_OFF + 16, gB + 16);
        cp_commit();
    };

    prefetch(0, 0);
    prefetch(1, 1);

    int st = 0;
    for (int kt = 0; kt < KT; ++kt) {
        cp_wait<1>();
        __syncthreads();

        const uint32_t base = sbase + st * STAGE_B;
#pragma unroll
        for (int ks = 0; ks < 2; ++ks) {
            uint32_t bf[2][4];
#pragma unroll
            for (int nf = 0; nf < 2; ++nf)
                ldmx4(bf[nf], base + B_OFF + (uint32_t)((bRow + nf * 16) * ROWB) +
                              (uint32_t)(ks * 16 + bHalf) * 2);
            uint32_t af[4][4];
#pragma unroll
            for (int mf = 0; mf < 4; ++mf)
                ldmx4(af[mf], base + A_OFF + (uint32_t)((aRow + mf * 16) * ROWB) +
                              (uint32_t)(ks * 16 + aHalf) * 2);
#pragma unroll
            for (int mf = 0; mf < 4; ++mf)
#pragma unroll
                for (int nr = 0; nr < 4; ++nr)
                    mma16816(acc[mf][nr], af[mf], bf[nr >> 1][(nr & 1) * 2],
                             bf[nr >> 1][(nr & 1) * 2 + 1]);
        }

        // prefetch into slot (kt+2)%3 == (kt-1)%3 — safe: the sync above
        // guarantees every thread finished compute of k-tile kt-1.
        if (kt + 2 < KT) prefetch(kt + 2, (kt + 2) % NSTAGE);
        else             cp_commit();   // keep group accounting aligned

        st = (st + 1) % NSTAGE;
    }

    // ---- epilogue (fp16 stores) ----
    const int g  = lane >> 2;
    const int qd = lane & 3;
#pragma unroll
    for (int mf = 0; mf < 4; ++mf) {
#pragma unroll
        for (int nr = 0; nr < 4; ++nr) {
#pragma unroll
            for (int half = 0; half < 2; ++half) {
                const int row = m0 + wm + mf * 16 + g + half * 8;
                const int col = n0 + wn + nr * 8 + qd * 2;
                float v0 = acc[mf][nr][half * 2 + 0];
                float v1 = acc[mf][nr][half * 2 + 1];
                if (act == ACT_ELU1) {
                    v0 = (v0 > 0.f) ? v0 + 1.f : expf(v0);
                    v1 = (v1 > 0.f) ? v1 + 1.f : expf(v1);
                } else if (act == ACT_RELU) {
                    v0 = fmaxf(v0, 0.f); v1 = fmaxf(v1, 0.f);
                }
                *(uint32_t*)&Ch[(size_t)row * NT + col] = pack2h(v0, v1);
            }
        }
    }
}

// Merged Q/K/V launch: blockIdx.z selects {Q, K, V}; all outputs fp16.
__global__ void __launch_bounds__(256)
gemm_qkv_kernel()
{
    extern __shared__ char smem[];
    const int z  = blockIdx.z;
    const int m0 = blockIdx.y * 128;
    const int n0 = blockIdx.x * 128;
    const __half* A = (z == 0) ? g_x16 : g_s16;
    const __half* W = (z == 0) ? g_Wq16 : (z == 1) ? g_Wk16 : g_Wv16;
    __half* C       = (z == 0) ? g_q16  : (z == 1) ? g_k16  : g_v16;
    const int act   = (z == 2) ? ACT_NONE : ACT_ELU1;
    gemm_core(A, nullptr, CD, CD, W, C, CD, act, smem, m0, n0);
}

// Generic single-GEMM launch.
__global__ void __launch_bounds__(256)
gemm_one_kernel(const __half* __restrict__ A1, const __half* __restrict__ A2,
                int K1, int K, const __half* __restrict__ Wh,
                __half* __restrict__ Ch, int NT, int act)
{
    extern __shared__ char smem[];
    gemm_core(A1, A2, K1, K, Wh, Ch, NT, act,
              smem, blockIdx.y * 128, blockIdx.x * 128);
}

// ---------------------------------------------------------------------------
// KV reduce — tensor-core K^T·V (proven R11 version).
// ---------------------------------------------------------------------------
#define KVROW 40

__global__ void __launch_bounds__(128)
kv_reduce_kernel()
{
    __shared__ __half KVsm[2][256][KVROW];

    const int nh = blockIdx.x;
    const int n  = nh / NH;
    const int h  = nh % NH;
    const int s0 = blockIdx.y * 256;
    const int tid  = threadIdx.x;
    const int wid  = tid >> 5;
    const int lane = tid & 31;

    const __half* Kb = g_k16 + (size_t)n * LSEQ * CD + (size_t)h * HD;
    const __half* Vb = g_v16 + (size_t)n * LSEQ * CD + (size_t)h * HD;

    for (int i = tid; i < 256 * 4; i += 128) {
        const int r = i >> 2;
        const int c = (i & 3) * 8;
        const size_t off = (size_t)(s0 + r) * CD + c;
        *(uint4*)&KVsm[0][r][c] = *(const uint4*)&Kb[off];
        *(uint4*)&KVsm[1][r][c] = *(const uint4*)&Vb[off];
    }
    __syncthreads();

    {
        float ksum = 0.0f;
        const int sb = wid * 64;
#pragma unroll 8
        for (int s = sb; s < sb + 64; ++s)
            ksum += __half2float(KVsm[0][s][lane]);
        atomicAdd(&g_Ksum[nh * HD + lane], ksum);
    }

    float acc[2][4][4];
#pragma unroll
    for (int i = 0; i < 2; ++i)
#pragma unroll
        for (int j = 0; j < 4; ++j)
#pragma unroll
            for (int r = 0; r < 4; ++r) acc[i][j][r] = 0.0f;

    const uint32_t kbase = smem_u32(&KVsm[0][0][0]);
    const uint32_t vbase = smem_u32(&KVsm[1][0][0]);
    const int q  = lane >> 3;
    const int i8 = lane & 7;

#pragma unroll
    for (int chunk = 0; chunk < 4; ++chunk) {
        const int sb = wid * 64 + chunk * 16;
        const int sA = sb + ((q >> 1) ? 8 : 0) + i8;
        uint32_t af[2][4];
#pragma unroll
        for (int mt = 0; mt < 2; ++mt) {
            const int col = mt * 16 + ((q & 1) ? 8 : 0);
            ldmx4t(af[mt], kbase + (uint32_t)(sA * KVROW + col) * 2);
        }
        const int sB = sb + ((q & 1) ? 8 : 0) + i8;
        uint32_t bf[2][4];
#pragma unroll
        for (int nf = 0; nf < 2; ++nf) {
            const int col = nf * 16 + ((q >> 1) ? 8 : 0);
            ldmx4t(bf[nf], vbase + (uint32_t)(sB * KVROW + col) * 2);
        }
#pragma unroll
        for (int mt = 0; mt < 2; ++mt)
#pragma unroll
            for (int nt = 0; nt < 4; ++nt)
                mma16816(acc[mt][nt], af[mt], bf[nt >> 1][(nt & 1) * 2],
                         bf[nt >> 1][(nt & 1) * 2 + 1]);
    }
    __syncthreads();

    float* Cred = (float*)&KVsm[0][0][0];
    const int g  = lane >> 2;
    const int qd = lane & 3;
#pragma unroll
    for (int mt = 0; mt < 2; ++mt)
#pragma unroll
        for (int nt = 0; nt < 4; ++nt)
#pragma unroll
            for (int c = 0; c < 4; ++c) {
                const int d = mt * 16 + g + ((c >> 1) ? 8 : 0);
                const int e = nt * 8 + qd * 2 + (c & 1);
                Cred[(wid * 32 + d) * 33 + e] = acc[mt][nt][c];
            }
    __syncthreads();

    for (int cell = tid; cell < 1024; cell += 128) {
        const int d = cell >> 5;
        const int e = cell & 31;
        const float ssum = Cred[(0 * 32 + d) * 33 + e] + Cred[(1 * 32 + d) * 33 + e]
                         + Cred[(2 * 32 + d) * 33 + e] + Cred[(3 * 32 + d) * 33 + e];
        atomicAdd(&g_KV[(size_t)nh * HD * HD + cell], ssum);
    }
}

// ---------------------------------------------------------------------------
// Attention apply: reads Q fp16; 4-row batching; warp == head.
// ---------------------------------------------------------------------------
__global__ void __launch_bounds__(256)
attn_apply_kernel()
{
    __shared__ float KVs[NH * HD * HD];
    __shared__ float KsumS[NH * HD];

    const int row0 = blockIdx.x * 64;
    const int n    = row0 / LSEQ;
    const int tid  = threadIdx.x;
    const int h    = tid >> 5;
    const int e    = tid & 31;

    const float* KVg = g_KV + (size_t)n * NH * HD * HD;
    for (int i = tid; i < NH * HD * HD / 4; i += 256)
        ((float4*)KVs)[i] = ((const float4*)KVg)[i];
    KsumS[tid] = g_Ksum[n * NH * HD + tid];
    __syncthreads();

    const float ks = KsumS[tid];
    const float* kvh = &KVs[h * HD * HD];

    for (int r = 0; r < 64; r += 4) {
        const size_t b0 = (size_t)(row0 + r) * CD;
        const float q0 = __half2float(g_q16[b0 + tid]);
        const float q1 = __half2float(g_q16[b0 + CD + tid]);
        const float q2 = __half2float(g_q16[b0 + 2 * CD + tid]);
        const float q3 = __half2float(g_q16[b0 + 3 * CD + tid]);

        float z0 = q0 * ks, z1 = q1 * ks, z2 = q2 * ks, z3 = q3 * ks;
#pragma unroll
        for (int o = 16; o > 0; o >>= 1) {
            z0 += __shfl_xor_sync(0xffffffff, z0, o);
            z1 += __shfl_xor_sync(0xffffffff, z1, o);
            z2 += __shfl_xor_sync(0xffffffff, z2, o);
            z3 += __shfl_xor_sync(0xffffffff, z3, o);
        }
        z0 = 1.0f / (z0 + 1e-6f);
        z1 = 1.0f / (z1 + 1e-6f);
        z2 = 1.0f / (z2 + 1e-6f);
        z3 = 1.0f / (z3 + 1e-6f);

        float a0 = 0.f, a1 = 0.f, a2 = 0.f, a3 = 0.f;
#pragma unroll
        for (int d = 0; d < HD; ++d) {
            const float kvv = kvh[d * HD + e];
            a0 = fmaf(__shfl_sync(0xffffffff, q0, d), kvv, a0);
            a1 = fmaf(__shfl_sync(0xffffffff, q1, d), kvv, a1);
            a2 = fmaf(__shfl_sync(0xffffffff, q2, d), kvv, a2);
            a3 = fmaf(__shfl_sync(0xffffffff, q3, d), kvv, a3);
        }
        g_a16[b0 + tid]          = __float2half_rn(a0 * z0);
        g_a16[b0 + CD + tid]     = __float2half_rn(a1 * z1);
        g_a16[b0 + 2 * CD + tid] = __float2half_rn(a2 * z2);
        g_a16[b0 + 3 * CD + tid] = __float2half_rn(a3 * z3);
    }
}

// ---------------------------------------------------------------------------
// LayerNorm variants (fp16 inputs)
// ---------------------------------------------------------------------------
__global__ void __launch_bounds__(256)
ln_f16_kernel(const __half* __restrict__ src, __half* __restrict__ o,
              const float* __restrict__ g, const float* __restrict__ b)
{
    const int row  = blockIdx.x * 8 + threadIdx.y;
    const int lane = threadIdx.x;
    const __half* p = src + (size_t)row * CD;

    float v[8];
    float s = 0.0f;
#pragma unroll
    for (int i = 0; i < 8; ++i) { v[i] = __half2float(p[i * 32 + lane]); s += v[i]; }
#pragma unroll
    for (int of = 16; of > 0; of >>= 1) s += __shfl_xor_sync(0xffffffff, s, of);
    const float mu = s * (1.0f / CD);

    float vs = 0.0f;
#pragma unroll
    for (int i = 0; i < 8; ++i) { const float d = v[i] - mu; vs = fmaf(d, d, vs); }
#pragma unroll
    for (int of = 16; of > 0; of >>= 1) vs += __shfl_xor_sync(0xffffffff, vs, of);
    const float rstd = rsqrtf(vs * (1.0f / CD) + 1e-7f);

#pragma unroll
    for (int i = 0; i < 8; ++i) {
        const int c = i * 32 + lane;
        o[(size_t)row * CD + c] =
            __float2half_rn((v[i] - mu) * rstd * g[c] + b[c]);
    }
}

__global__ void __launch_bounds__(256)
ln_res_kernel(const __half* __restrict__ src, const float* __restrict__ x,
              float* __restrict__ dst,
              const float* __restrict__ g, const float* __restrict__ b)
{
    const int row  = blockIdx.x * 8 + threadIdx.y;
    const int lane = threadIdx.x;
    const __half* p = src + (size_t)row * CD;

    float v[8];
    float s = 0.0f;
#pragma unroll
    for (int i = 0; i < 8; ++i) { v[i] = __half2float(p[i * 32 + lane]); s += v[i]; }
#pragma unroll
    for (int of = 16; of > 0; of >>= 1) s += __shfl_xor_sync(0xffffffff, s, of);
    const float mu = s * (1.0f / CD);

    float vs = 0.0f;
#pragma unroll
    for (int i = 0; i < 8; ++i) { const float d = v[i] - mu; vs = fmaf(d, d, vs); }
#pragma unroll
    for (int of = 16; of > 0; of >>= 1) vs += __shfl_xor_sync(0xffffffff, vs, of);
    const float rstd = rsqrtf(vs * (1.0f / CD) + 1e-7f);

#pragma unroll
    for (int i = 0; i < 8; ++i) {
        const int c = i * 32 + lane;
        dst[(size_t)row * CD + c] =
            (v[i] - mu) * rstd * g[c] + b[c] + x[(size_t)row * CD + c];
    }
}

// ---------------------------------------------------------------------------
// Launch
// ---------------------------------------------------------------------------
extern "C" void kernel_launch(void* const* d_in, const int* in_sizes, int n_in,
                              void* d_out, int out_size)
{
    const float* x      = (const float*)d_in[0];
    const float* source = (const float*)d_in[1];
    const float* Wq     = (const float*)d_in[2];
    const float* Wk     = (const float*)d_in[3];
    const float* Wv     = (const float*)d_in[4];
    const float* Wmerge = (const float*)d_in[5];
    const float* Wmlp1  = (const float*)d_in[6];
    const float* Wmlp2  = (const float*)d_in[7];
    const float* ln1_g  = (const float*)d_in[8];
    const float* ln1_b  = (const float*)d_in[9];
    const float* ln2_g  = (const float*)d_in[10];
    const float* ln2_b  = (const float*)d_in[11];
    float* out = (float*)d_out;

    __half *x16, *a16, *mg16, *m16, *h16, *m216;
    __half *W16m, *W161, *W162;
    cudaGetSymbolAddress((void**)&x16,  g_x16);
    cudaGetSymbolAddress((void**)&a16,  g_a16);
    cudaGetSymbolAddress((void**)&mg16, g_mg16);
    cudaGetSymbolAddress((void**)&m16,  g_m16);
    cudaGetSymbolAddress((void**)&h16,  g_h16);
    cudaGetSymbolAddress((void**)&m216, g_m2_16);
    cudaGetSymbolAddress((void**)&W16m, g_Wm16);
    cudaGetSymbolAddress((void**)&W161, g_W116);
    cudaGetSymbolAddress((void**)&W162, g_W216);

    static bool smem_set = false;
    if (!smem_set) {
        cudaFuncSetAttribute((const void*)gemm_qkv_kernel,
                             cudaFuncAttributeMaxDynamicSharedMemorySize, SMEM_SZ);
        cudaFuncSetAttribute((const void*)gemm_one_kernel,
                             cudaFuncAttributeMaxDynamicSharedMemorySize, SMEM_SZ);
        smem_set = true;
    }

    const int GM = MTOT / 128;
    const dim3 gqkv(2, GM, 3);
    const dim3 g256(2, GM);
    const dim3 g512(4, GM);

    // 1: convert activations (x + source) to fp16
    cvt_act_kernel<<<dim3((unsigned)(MC / 4 / 256), 2), 256>>>(x, source);
    // 2: convert all weights to fp16 + zero KV accumulators
    cvt_w_kernel<<<640, 256>>>(Wq, Wk, Wv, Wmerge, Wmlp1, Wmlp2);

    // 3: Q/K/V GEMMs in one launch (all fp16 out)
    gemm_qkv_kernel<<<gqkv, 256, SMEM_SZ>>>();

    // 4: KV / Ksum via tensor cores
    kv_reduce_kernel<<<dim3(NB * NH, LSEQ / 256), 128>>>();
    // 5: attention apply -> fp16
    attn_apply_kernel<<<MTOT / 64, 256>>>();

    // 6: msg = attn @ Wmerge^T -> fp16
    gemm_one_kernel<<<g256, 256, SMEM_SZ>>>(
        a16, nullptr, CD, CD, W16m, mg16, CD, ACT_NONE);
    // 7: LN1 -> fp16
    ln_f16_kernel<<<MTOT / 8, dim3(32, 8)>>>(mg16, m16, ln1_g, ln1_b);

    // 8: h = relu([x | msg] @ Wmlp1^T) -> fp16
    gemm_one_kernel<<<g512, 256, SMEM_SZ>>>(
        x16, m16, CD, 2 * CD, W161, h16, 2 * CD, ACT_RELU);

    // 9: msg2 = h @ Wmlp2^T -> fp16
    gemm_one_kernel<<<g256, 256, SMEM_SZ>>>(
        h16, nullptr, 2 * CD, 2 * CD, W162, m216, CD, ACT_NONE);
    // 10: out = x + LN2(msg2)
    ln_res_kernel<<<MTOT / 8, dim3(32, 8)>>>(m216, x, out, ln2_g, ln2_b);
}